// round 1
// baseline (speedup 1.0000x reference)
#include <cuda_runtime.h>
#include <math.h>

#define BS 4
#define LEN 2048
#define CIN 32
#define COUT 32
#define HIDDIM 64
#define KTAP 8
#define PADL 7
#define NPOS (BS * LEN)          // 8192 positions
#define RDIM (CIN * HIDDIM)      // 2048 contraction dim
#define EPSV 1e-5f

// Scratch (allocation-free rule: device globals)
__device__ float  g_M[16777216];        // [NPOS][RDIM] = 64 MB
__device__ float  g_fsum[NPOS * CIN];   // [NPOS][CIN]
__device__ double g_stats[2 * COUT];    // per-channel sum / sumsq

__global__ void k_zero() {
    int i = threadIdx.x;
    if (i < 2 * COUT) g_stats[i] = 0.0;
}

// non_pad_mask dtype hedge: byte 1 nonzero <=> 1-byte storage (mask[0][1] is
// guaranteed true since lengths >= L/2). Otherwise 4-byte words (int32 or
// float32 -> nonzero word test works for both).
__device__ __forceinline__ bool mask_at(const void* m, int idx, bool byte_mode) {
    if (byte_mode) return ((const unsigned char*)m)[idx] != 0;
    return ((const unsigned int*)m)[idx] != 0u;
}

// ---------------------------------------------------------------------------
// K1: per position p=(b,t), accumulate M[c,j] = sum_k f_k[c] * h_k[j]
//     warp per position; lane = c; h broadcast via per-warp smem buffer.
// ---------------------------------------------------------------------------
__global__ __launch_bounds__(256) void k1(const float* __restrict__ times,
                                          const float* __restrict__ features,
                                          const void*  __restrict__ mask,
                                          const float* __restrict__ W1,
                                          const float* __restrict__ b1) {
    __shared__ float W1s[CIN * HIDDIM];
    __shared__ float b1s[HIDDIM];
    __shared__ float hbuf[8][HIDDIM];

    int tid = threadIdx.x;
    for (int i = tid; i < CIN * HIDDIM; i += 256) W1s[i] = W1[i];
    if (tid < HIDDIM) b1s[tid] = b1[tid];
    __syncthreads();

    int wid  = tid >> 5;
    int lane = tid & 31;
    int p = blockIdx.x * 8 + wid;   // global position
    int b = p >> 11;
    int t = p & (LEN - 1);

    bool byte_mode = ((const unsigned char*)mask)[1] != 0;
    bool mask_t = mask_at(mask, p, byte_mode);
    float t_here = times[p];

    // temporal encoding constants for this lane (channel i = lane):
    // pos[i] = 10000^((i/2)/16);  te[i] = sin(dt/pos + phase), phase=pi/2 for odd i
    float inv_pos = __expf(-(float)(lane >> 1) * (9.210340371976184f / 16.0f));
    float phase   = (lane & 1) ? 1.5707963267948966f : 0.0f;

    float Mreg[HIDDIM];
#pragma unroll
    for (int j = 0; j < HIDDIM; j++) Mreg[j] = 0.0f;
    float fsum = 0.0f;

    for (int k = 0; k < KTAP; k++) {
        int idx = t - PADL + k;
        bool dm = mask_t && (idx >= 0);
        if (dm) dm = mask_at(mask, b * LEN + idx, byte_mode);
        if (!dm) continue;   // warp-uniform predicate (lane-invariant)

        float dt = t_here - times[b * LEN + idx];
        float te = __sinf(dt * inv_pos + phase);

        // h[j] = relu(b1[j] + sum_i te[i]*W1[i,j]); lane computes j=lane, lane+32
        float ha = b1s[lane], hb = b1s[lane + 32];
#pragma unroll
        for (int i = 0; i < CIN; i++) {
            float tei = __shfl_sync(0xffffffffu, te, i);
            ha += tei * W1s[i * HIDDIM + lane];
            hb += tei * W1s[i * HIDDIM + lane + 32];
        }
        ha = fmaxf(ha, 0.0f);
        hb = fmaxf(hb, 0.0f);

        __syncwarp();                       // prior reads of hbuf done
        hbuf[wid][lane]      = ha;
        hbuf[wid][lane + 32] = hb;
        __syncwarp();

        float f = features[(size_t)(b * LEN + idx) * CIN + lane];
        fsum += f;
#pragma unroll
        for (int j = 0; j < HIDDIM; j++) Mreg[j] += f * hbuf[wid][j];
    }

    // store M row: r = j*32 + c  (c = lane) -> coalesced 128B per j
    float* mout = g_M + (size_t)p * RDIM + lane;
#pragma unroll
    for (int j = 0; j < HIDDIM; j++) mout[j * 32] = Mreg[j];
    g_fsum[p * CIN + lane] = fsum;
}

// ---------------------------------------------------------------------------
// K2: out[p,o] = M[p,:] @ W2'[:,o] + fsum[p,:]@b2mat + feat[p,:]@W_skip + b_skip
//     + per-channel stats accumulation. W2 chunked through smem.
//     block = 512 threads = 16 warps = 16 positions; lane = o.
// ---------------------------------------------------------------------------
#define RC 256
__global__ __launch_bounds__(512) void k2(const float* __restrict__ features,
                                          const float* __restrict__ W2,
                                          const float* __restrict__ b2,
                                          const float* __restrict__ Wskip,
                                          const float* __restrict__ bskip,
                                          float* __restrict__ out) {
    __shared__ float w2s[RC * 32];
    __shared__ float b2s[CIN * COUT];
    __shared__ float wsk[CIN * COUT];
    __shared__ float bsk[COUT];
    __shared__ float ssum[COUT], ssq[COUT];

    int tid = threadIdx.x;
    for (int i = tid; i < CIN * COUT; i += 512) { b2s[i] = b2[i]; wsk[i] = Wskip[i]; }
    if (tid < COUT) { bsk[tid] = bskip[tid]; ssum[tid] = 0.0f; ssq[tid] = 0.0f; }

    int wid = tid >> 5, lane = tid & 31;
    int p = blockIdx.x * 16 + wid;
    const float* mrow = g_M + (size_t)p * RDIM;
    float acc = 0.0f;

    for (int ch = 0; ch < RDIM / RC; ch++) {
        __syncthreads();   // also orders the init stores above on first iter
        // stage W2 chunk: row r = ch*RC+rl pairs M[r=j*32+c] with W2[j*1024 + c*32 + o]
        for (int s = 0; s < RC * 32; s += 512) {
            int li = s + tid;
            int rl = li >> 5, o = li & 31;
            int r  = ch * RC + rl;
            w2s[li] = W2[(r >> 5) * (CIN * COUT) + (r & 31) * COUT + o];
        }
        __syncthreads();

        const float4* mp = (const float4*)(mrow + ch * RC);
#pragma unroll 4
        for (int q = 0; q < RC / 4; q++) {
            float4 mv = mp[q];   // warp-uniform address -> broadcast load
            acc += mv.x * w2s[(q * 4 + 0) * 32 + lane];
            acc += mv.y * w2s[(q * 4 + 1) * 32 + lane];
            acc += mv.z * w2s[(q * 4 + 2) * 32 + lane];
            acc += mv.w * w2s[(q * 4 + 3) * 32 + lane];
        }
    }

    // augmented terms: fsum @ b2mat  +  feat @ W_skip  +  b_skip
    const float4* fs = (const float4*)(g_fsum + p * CIN);
    const float4* fv = (const float4*)(features + (size_t)p * CIN);
#pragma unroll
    for (int q = 0; q < CIN / 4; q++) {
        float4 a = fs[q];
        float4 c = fv[q];
        acc += a.x * b2s[(q * 4 + 0) * 32 + lane];
        acc += a.y * b2s[(q * 4 + 1) * 32 + lane];
        acc += a.z * b2s[(q * 4 + 2) * 32 + lane];
        acc += a.w * b2s[(q * 4 + 3) * 32 + lane];
        acc += c.x * wsk[(q * 4 + 0) * 32 + lane];
        acc += c.y * wsk[(q * 4 + 1) * 32 + lane];
        acc += c.z * wsk[(q * 4 + 2) * 32 + lane];
        acc += c.w * wsk[(q * 4 + 3) * 32 + lane];
    }
    acc += bsk[lane];

    out[(size_t)p * COUT + lane] = acc;

    // per-channel stats: smem float partials, then global double atomics
    atomicAdd(&ssum[lane], acc);
    atomicAdd(&ssq[lane], acc * acc);
    __syncthreads();
    if (tid < COUT) {
        atomicAdd(&g_stats[tid],        (double)ssum[tid]);
        atomicAdd(&g_stats[COUT + tid], (double)ssq[tid]);
    }
}

// ---------------------------------------------------------------------------
// K3: LayerNorm finalize in place
// ---------------------------------------------------------------------------
__global__ void k3(float* __restrict__ out,
                   const float* __restrict__ gamma,
                   const float* __restrict__ beta) {
    int e = blockIdx.x * blockDim.x + threadIdx.x;
    if (e >= NPOS * COUT) return;
    int o = e & (COUT - 1);
    double n = (double)NPOS;
    double mean = g_stats[o] / n;
    double var  = g_stats[COUT + o] / n - mean * mean;
    float rstd = rsqrtf((float)var + EPSV);
    out[e] = gamma[o] * (out[e] - (float)mean) * rstd + beta[o];
}

// ---------------------------------------------------------------------------
extern "C" void kernel_launch(void* const* d_in, const int* in_sizes, int n_in,
                              void* d_out, int out_size) {
    const float* times    = (const float*)d_in[0];
    const float* features = (const float*)d_in[1];
    const void*  mask     = d_in[2];
    const float* W1    = (const float*)d_in[3];
    const float* b1    = (const float*)d_in[4];
    const float* W2    = (const float*)d_in[5];
    const float* b2    = (const float*)d_in[6];
    const float* Wskip = (const float*)d_in[7];
    const float* bskip = (const float*)d_in[8];
    const float* gamma = (const float*)d_in[9];
    const float* beta  = (const float*)d_in[10];
    float* out = (float*)d_out;

    k_zero<<<1, 64>>>();
    k1<<<NPOS / 8, 256>>>(times, features, mask, W1, b1);
    k2<<<NPOS / 16, 512>>>(features, W2, b2, Wskip, bskip, out);
    k3<<<(NPOS * COUT + 255) / 256, 256>>>(out, gamma, beta);
}

// round 2
// speedup vs baseline: 4.0368x; 4.0368x over previous
#include <cuda_runtime.h>
#include <math.h>

#define BS 4
#define LEN 2048
#define CIN 32
#define COUT 32
#define HIDDIM 64
#define KTAP 8
#define PADL 7
#define NPOS (BS * LEN)          // 8192 positions
#define RDIM (CIN * HIDDIM)      // 2048 contraction dim
#define EPSV 1e-5f
#define NW 8                      // warps / positions per block

__device__ double g_stats[2 * COUT];    // per-channel sum / sumsq

__global__ void k_zero() {
    int i = threadIdx.x;
    if (i < 2 * COUT) g_stats[i] = 0.0;
}

// non_pad_mask dtype hedge: byte 1 nonzero <=> 1-byte storage (mask[0][1] is
// guaranteed true since lengths >= L/2). Otherwise 4-byte words (int32 or
// float32 -> nonzero word works for both).
__device__ __forceinline__ bool mask_at(const void* m, int idx, bool byte_mode) {
    if (byte_mode) return ((const unsigned char*)m)[idx] != 0;
    return ((const unsigned int*)m)[idx] != 0u;
}

struct SmemT {
    float W1p[CIN * HIDDIM];     // paired: [(ii*32+ln)*2 + h] = W1[ii*64+ln+h*32]
    float b1s[HIDDIM];
    float hbuf[NW][HIDDIM];
    float b2s[CIN * COUT];
    float wsk[CIN * COUT];
    float bsk[COUT];
    float ff[NW][CIN];           // features at position (for skip term)
    float fs[NW][CIN];           // fsum per channel
    float red[NW][NW][COUT];     // cross-warp partials [src_warp][pos][o]
    float ssum[COUT], ssq[COUT];
    int   pflag[NW];
    float Ms[NW][RDIM];          // M rows, r = j*32 + c   (64 KB)
};

// ---------------------------------------------------------------------------
// Fused kernel: phase A builds M (warp per position), phase B does the
// [8 x 2048] @ [2048 x 32] contraction with W2 strips in registers.
// ---------------------------------------------------------------------------
__global__ __launch_bounds__(256) void kfused(const float* __restrict__ times,
                                              const float* __restrict__ features,
                                              const void*  __restrict__ mask,
                                              const float* __restrict__ W1,
                                              const float* __restrict__ b1,
                                              const float* __restrict__ W2,
                                              const float* __restrict__ b2,
                                              const float* __restrict__ Wskip,
                                              const float* __restrict__ bskip,
                                              float* __restrict__ out) {
    extern __shared__ char smem_raw[];
    SmemT* s = (SmemT*)smem_raw;

    int tid  = threadIdx.x;
    int wid  = tid >> 5;
    int lane = tid & 31;

    // ---- stage constants ----
    for (int i = tid; i < CIN * HIDDIM; i += 256) {
        int q = i >> 1, h = i & 1;
        int ii = q >> 5, ln = q & 31;
        s->W1p[i] = W1[ii * HIDDIM + ln + h * 32];
    }
    for (int i = tid; i < CIN * COUT; i += 256) {
        s->b2s[i] = b2[i];
        s->wsk[i] = Wskip[i];
    }
    if (tid < HIDDIM) s->b1s[tid] = b1[tid];
    if (tid < COUT) {
        s->bsk[tid]  = bskip[tid];
        s->ssum[tid] = 0.0f;
        s->ssq[tid]  = 0.0f;
    }
    __syncthreads();

    // ---- phase A: build M row for position p ----
    int p = blockIdx.x * NW + wid;
    int b = p >> 11;
    int t = p & (LEN - 1);

    bool byte_mode = ((const unsigned char*)mask)[1] != 0;
    bool mask_t = mask_at(mask, p, byte_mode);
    float t_here = times[p];

    // te[i] = sin(dt/pos_i + phase_i); lane = channel i
    float inv_pos = __expf(-(float)(lane >> 1) * (9.210340371976184f / 16.0f));
    float phase   = (lane & 1) ? 1.5707963267948966f : 0.0f;

    s->ff[wid][lane] = features[(size_t)p * CIN + lane];

    float Mreg[HIDDIM];
#pragma unroll
    for (int j = 0; j < HIDDIM; j++) Mreg[j] = 0.0f;
    float fsum = 0.0f;
    bool any = false;

    for (int k = 0; k < KTAP; k++) {
        int idx = t - PADL + k;
        bool dm = mask_t && (idx >= 0);
        if (dm) dm = mask_at(mask, b * LEN + idx, byte_mode);
        if (!dm) continue;               // warp-uniform
        any = true;

        float dt = t_here - times[b * LEN + idx];
        float te = __sinf(dt * inv_pos + phase);

        float ha = s->b1s[lane], hb = s->b1s[lane + 32];
#pragma unroll
        for (int ii = 0; ii < CIN; ii++) {
            float tei = __shfl_sync(0xffffffffu, te, ii);
            float2 w = *(const float2*)&s->W1p[(ii * 32 + lane) * 2];
            ha += tei * w.x;
            hb += tei * w.y;
        }
        ha = fmaxf(ha, 0.0f);
        hb = fmaxf(hb, 0.0f);

        __syncwarp();                    // prior hbuf reads complete
        s->hbuf[wid][lane]      = ha;
        s->hbuf[wid][lane + 32] = hb;
        __syncwarp();

        float f = features[(size_t)(b * LEN + idx) * CIN + lane];
        fsum += f;
#pragma unroll
        for (int q = 0; q < HIDDIM / 4; q++) {
            float4 h4 = *(const float4*)&s->hbuf[wid][q * 4];
            Mreg[q * 4 + 0] += f * h4.x;
            Mreg[q * 4 + 1] += f * h4.y;
            Mreg[q * 4 + 2] += f * h4.z;
            Mreg[q * 4 + 3] += f * h4.w;
        }
    }

    // park M row: r = j*32 + c  (c = lane) -> conflict-free STS
#pragma unroll
    for (int j = 0; j < HIDDIM; j++) s->Ms[wid][j * 32 + lane] = Mreg[j];
    s->fs[wid][lane] = fsum;
    if (lane == 0) s->pflag[wid] = any ? 1 : 0;
    __syncthreads();

    // ---- phase B: acc[p] += Ms[p, rstrip] @ W2'[rstrip, lane] ----
    // warp wid owns r in [wid*256, wid*256+256); W2'[r][o] = W2[(r>>5)*1024+(r&31)*32+o]
    float acc[NW];
#pragma unroll
    for (int q = 0; q < NW; q++) acc[q] = 0.0f;

    int rbase = wid * 256;
    for (int cc = 0; cc < 4; cc++) {
        int r0 = rbase + cc * 64;
        float wreg[64];
#pragma unroll
        for (int q = 0; q < 64; q++) {
            int r = r0 + q;
            wreg[q] = W2[(r >> 5) * (CIN * COUT) + (r & 31) * COUT + lane];
        }
#pragma unroll
        for (int pp = 0; pp < NW; pp++) {
            if (!s->pflag[pp]) continue;      // warp-uniform skip
            const float4* m4 = (const float4*)&s->Ms[pp][r0];
#pragma unroll
            for (int q4 = 0; q4 < 16; q4++) {
                float4 m = m4[q4];            // uniform addr -> broadcast LDS.128
                acc[pp] += m.x * wreg[q4 * 4 + 0];
                acc[pp] += m.y * wreg[q4 * 4 + 1];
                acc[pp] += m.z * wreg[q4 * 4 + 2];
                acc[pp] += m.w * wreg[q4 * 4 + 3];
            }
        }
    }
#pragma unroll
    for (int pp = 0; pp < NW; pp++) s->red[wid][pp][lane] = acc[pp];
    __syncthreads();

    // ---- epilogue: warp wid finalizes its own position ----
    float o = 0.0f;
#pragma unroll
    for (int w = 0; w < NW; w++) o += s->red[w][wid][lane];
#pragma unroll
    for (int c = 0; c < CIN; c++) {
        o += s->fs[wid][c] * s->b2s[c * COUT + lane];
        o += s->ff[wid][c] * s->wsk[c * COUT + lane];
    }
    o += s->bsk[lane];

    out[(size_t)p * COUT + lane] = o;

    atomicAdd(&s->ssum[lane], o);
    atomicAdd(&s->ssq[lane], o * o);
    __syncthreads();
    if (tid < COUT) {
        atomicAdd(&g_stats[tid],        (double)s->ssum[tid]);
        atomicAdd(&g_stats[COUT + tid], (double)s->ssq[tid]);
    }
}

// ---------------------------------------------------------------------------
// K3: LayerNorm finalize in place (float4 vectorized)
// ---------------------------------------------------------------------------
__global__ void k3(float* __restrict__ out,
                   const float* __restrict__ gamma,
                   const float* __restrict__ beta) {
    int e4 = blockIdx.x * blockDim.x + threadIdx.x;   // float4 index
    if (e4 >= NPOS * COUT / 4) return;
    int o0 = (e4 * 4) & (COUT - 1);
    double n = (double)NPOS;
    float4 v = ((const float4*)out)[e4];
    float r[4] = {v.x, v.y, v.z, v.w};
#pragma unroll
    for (int q = 0; q < 4; q++) {
        int o = o0 + q;
        double mean = g_stats[o] / n;
        double var  = g_stats[COUT + o] / n - mean * mean;
        float rstd = rsqrtf((float)var + EPSV);
        r[q] = gamma[o] * (r[q] - (float)mean) * rstd + beta[o];
    }
    ((float4*)out)[e4] = make_float4(r[0], r[1], r[2], r[3]);
}

// ---------------------------------------------------------------------------
extern "C" void kernel_launch(void* const* d_in, const int* in_sizes, int n_in,
                              void* d_out, int out_size) {
    const float* times    = (const float*)d_in[0];
    const float* features = (const float*)d_in[1];
    const void*  mask     = d_in[2];
    const float* W1    = (const float*)d_in[3];
    const float* b1    = (const float*)d_in[4];
    const float* W2    = (const float*)d_in[5];
    const float* b2    = (const float*)d_in[6];
    const float* Wskip = (const float*)d_in[7];
    const float* bskip = (const float*)d_in[8];
    const float* gamma = (const float*)d_in[9];
    const float* beta  = (const float*)d_in[10];
    float* out = (float*)d_out;

    cudaFuncSetAttribute(kfused, cudaFuncAttributeMaxDynamicSharedMemorySize,
                         (int)sizeof(SmemT));

    k_zero<<<1, 64>>>();
    kfused<<<NPOS / NW, 256, sizeof(SmemT)>>>(times, features, mask, W1, b1,
                                              W2, b2, Wskip, bskip, out);
    k3<<<(NPOS * COUT / 4 + 255) / 256, 256>>>(out, gamma, beta);
}

// round 4
// speedup vs baseline: 4.4004x; 1.0901x over previous
#include <cuda_runtime.h>
#include <math.h>

#define BS 4
#define LEN 2048
#define CIN 32
#define COUT 32
#define HIDDIM 64
#define KTAP 8
#define PADL 7
#define NPOS (BS * LEN)
#define RDIM (CIN * HIDDIM)      // 2048
#define EPSV 1e-5f
#define NWB 16                    // positions / warps per block
#define THREADS 512
#define NBLK (NPOS / NWB)         // 512
#define MSPITCH 34                // u64 pitch per channel (pad: bank spread + 16B align)

typedef unsigned long long u64;

__device__ double g_stats[2 * COUT];
__device__ int    g_sync;

// ---- register-pure packed helpers (no memory access in asm => safe) ----
#define FMA2(d, a, b, c) \
    asm("fma.rn.f32x2 %0, %1, %2, %3;" : "=l"(d) : "l"(a), "l"(b), "l"(c))

__device__ __forceinline__ u64 pack2(float x, float y) {
    u64 d; asm("mov.b64 %0, {%1, %2};" : "=l"(d) : "f"(x), "f"(y)); return d;
}
__device__ __forceinline__ u64 packdup(float x) {
    u64 d; asm("mov.b64 %0, {%1, %1};" : "=l"(d) : "f"(x)); return d;
}
__device__ __forceinline__ void unpack2(u64 v, float& x, float& y) {
    asm("mov.b64 {%0, %1}, %2;" : "=f"(x), "=f"(y) : "l"(v));
}

// mask dtype hedge (byte 1 nonzero <=> 1-byte storage; else 4-byte words)
__device__ __forceinline__ bool mask_at(const void* m, int idx, bool byte_mode) {
    if (byte_mode) return ((const unsigned char*)m)[idx] != 0;
    return ((const unsigned int*)m)[idx] != 0u;
}

struct SmemT {
    u64   W1u[CIN * 32];          // [i*32+ln] = (W1[i][2ln], W1[i][2ln+1])   8KB
    u64   b1u[32];                // (b1[2ln], b1[2ln+1])
    u64   te2u[NWB][32];          // duplicated te per channel                4KB
    u64   hbufu[NWB][32];         // [q] = (h[2q], h[2q+1])                   4KB
    float b2s[CIN * COUT];        // 4KB
    float wsk[CIN * COUT];        // 4KB
    float bsk[COUT];
    float ff[NWB][CIN];           // 2KB
    float fs[NWB][CIN];           // 2KB
    float red[NWB][NWB][COUT];    // 32KB
    float ssum[COUT], ssq[COUT];
    int   pflag[NWB];
    u64   Msu[NWB][CIN * MSPITCH]; // [c*34+q] = (M[c][2q], M[c][2q+1])     136KB
};

__global__ __launch_bounds__(THREADS, 1)
void kfused(const float* __restrict__ times,
            const float* __restrict__ features,
            const void*  __restrict__ mask,
            const float* __restrict__ W1,
            const float* __restrict__ b1,
            const float* __restrict__ W2,
            const float* __restrict__ b2,
            const float* __restrict__ Wskip,
            const float* __restrict__ bskip,
            float* __restrict__ out) {
    extern __shared__ char smem_raw[];
    SmemT* s = (SmemT*)smem_raw;

    int tid  = threadIdx.x;
    int wid  = tid >> 5;
    int lane = tid & 31;

    // ---- stage constants (W1 pairs are memory-adjacent -> direct u64 copy) ----
    const u64* W1as = (const u64*)W1;
    for (int i = tid; i < CIN * 32; i += THREADS) s->W1u[i] = W1as[i];
    for (int i = tid; i < CIN * COUT; i += THREADS) {
        s->b2s[i] = b2[i];
        s->wsk[i] = Wskip[i];
    }
    if (tid < 32) {
        s->b1u[tid]  = ((const u64*)b1)[tid];
        s->bsk[tid]  = bskip[tid];
        s->ssum[tid] = 0.0f;
        s->ssq[tid]  = 0.0f;
    }
    __syncthreads();

    // ================= phase A: build M row (warp per position) ============
    int p = blockIdx.x * NWB + wid;
    int b = p >> 11;
    int t = p & (LEN - 1);

    bool byte_mode = ((const unsigned char*)mask)[1] != 0;
    bool mask_t = mask_at(mask, p, byte_mode);
    float t_here = times[p];

    // lane = channel i for te / f loads
    float inv_pos = __expf(-(float)(lane >> 1) * (9.210340371976184f / 16.0f));
    float phase   = (lane & 1) ? 1.5707963267948966f : 0.0f;

    s->ff[wid][lane] = features[(size_t)p * CIN + lane];

    u64 Macc[32];                 // [q] = (M[lane][2q], M[lane][2q+1])  (j pairs)
#pragma unroll
    for (int q = 0; q < 32; q++) Macc[q] = 0ull;
    float fsum = 0.0f;
    bool any = false;

    for (int k = 0; k < KTAP; k++) {
        int idx = t - PADL + k;
        bool dm = mask_t && (idx >= 0);
        if (dm) dm = mask_at(mask, b * LEN + idx, byte_mode);
        if (!dm) continue;                    // warp-uniform
        any = true;

        float dt = t_here - times[b * LEN + idx];
        float te = __sinf(dt * inv_pos + phase);

        __syncwarp();                         // prior te2u/hbufu reads complete
        s->te2u[wid][lane] = packdup(te);
        __syncwarp();

        // h pair (h[2lane], h[2lane+1]) via packed FMA; te broadcast from smem
        u64 hh = s->b1u[lane];
#pragma unroll
        for (int i = 0; i < CIN; i++) {
            u64 teb = s->te2u[wid][i];            // broadcast LDS.64
            u64 w   = s->W1u[i * 32 + lane];
            FMA2(hh, teb, w, hh);
        }
        float ha, hb;
        unpack2(hh, ha, hb);
        ha = fmaxf(ha, 0.0f);
        hb = fmaxf(hb, 0.0f);

        __syncwarp();
        s->hbufu[wid][lane] = pack2(ha, hb);      // (h[2lane], h[2lane+1])
        __syncwarp();

        float f = features[(size_t)(b * LEN + idx) * CIN + lane];
        fsum += f;
        u64 f2 = packdup(f);
        const ulonglong2* hp2 = (const ulonglong2*)&s->hbufu[wid][0];
#pragma unroll
        for (int q2 = 0; q2 < 16; q2++) {
            ulonglong2 hp = hp2[q2];              // broadcast LDS.128
            FMA2(Macc[2 * q2],     f2, hp.x, Macc[2 * q2]);
            FMA2(Macc[2 * q2 + 1], f2, hp.y, Macc[2 * q2 + 1]);
        }
    }

    // park M: channel-major, u64-typed (no unpack) — lane = channel
#pragma unroll
    for (int q = 0; q < 32; q++) s->Msu[wid][lane * MSPITCH + q] = Macc[q];
    s->fs[wid][lane] = fsum;
    if (lane == 0) s->pflag[wid] = any ? 1 : 0;
    __syncthreads();

    // ================= phase B: [16 x 2048] @ [2048 x 32] ==================
    // warp wid owns channels c = 2*wid, 2*wid+1 (64 j's each).
    u64 acc2[NWB];
#pragma unroll
    for (int q = 0; q < NWB; q++) acc2[q] = 0ull;

    for (int cc = 0; cc < 4; cc++) {
        int c  = 2 * wid + (cc >> 1);
        int j0 = (cc & 1) * 32;
        int jb2 = (cc & 1) * 16;                  // u64 offset of j0 within channel
        // wq[q] = (W2[j0+2q][c*32+o], W2[j0+2q+1][c*32+o]), o = lane
        u64 wq[16];
        const float* w2base = W2 + (size_t)j0 * (CIN * COUT) + c * COUT + lane;
#pragma unroll
        for (int q = 0; q < 16; q++) {
            float w0 = w2base[(2 * q) * (CIN * COUT)];
            float w1 = w2base[(2 * q + 1) * (CIN * COUT)];
            wq[q] = pack2(w0, w1);
        }
#pragma unroll
        for (int pp = 0; pp < NWB; pp++) {
            if (!s->pflag[pp]) continue;          // warp-uniform skip
            const ulonglong2* mp = (const ulonglong2*)&s->Msu[pp][c * MSPITCH + jb2];
#pragma unroll
            for (int q2 = 0; q2 < 8; q2++) {
                ulonglong2 m = mp[q2];            // broadcast LDS.128
                FMA2(acc2[pp], m.x, wq[2 * q2],     acc2[pp]);
                FMA2(acc2[pp], m.y, wq[2 * q2 + 1], acc2[pp]);
            }
        }
    }
#pragma unroll
    for (int pp = 0; pp < NWB; pp++) {
        float lo, hi;
        unpack2(acc2[pp], lo, hi);
        s->red[wid][pp][lane] = lo + hi;
    }
    __syncthreads();

    // ================= epilogue: warp wid finalizes its position ===========
    float o = 0.0f;
#pragma unroll
    for (int w = 0; w < NWB; w++) o += s->red[w][wid][lane];

    const float4* fs4 = (const float4*)&s->fs[wid][0];
    const float4* ff4 = (const float4*)&s->ff[wid][0];
#pragma unroll
    for (int q = 0; q < CIN / 4; q++) {
        float4 a = fs4[q];
        float4 cf = ff4[q];
        o += a.x  * s->b2s[(q * 4 + 0) * 32 + lane];
        o += a.y  * s->b2s[(q * 4 + 1) * 32 + lane];
        o += a.z  * s->b2s[(q * 4 + 2) * 32 + lane];
        o += a.w  * s->b2s[(q * 4 + 3) * 32 + lane];
        o += cf.x * s->wsk[(q * 4 + 0) * 32 + lane];
        o += cf.y * s->wsk[(q * 4 + 1) * 32 + lane];
        o += cf.z * s->wsk[(q * 4 + 2) * 32 + lane];
        o += cf.w * s->wsk[(q * 4 + 3) * 32 + lane];
    }
    o += s->bsk[lane];

    out[(size_t)p * COUT + lane] = o;

    atomicAdd(&s->ssum[lane], o);
    atomicAdd(&s->ssq[lane], o * o);
    __syncthreads();
    if (tid < COUT) {
        atomicAdd(&g_stats[tid],        (double)s->ssum[tid]);
        atomicAdd(&g_stats[COUT + tid], (double)s->ssq[tid]);
    }
}

// ---------------------------------------------------------------------------
// K3: LayerNorm finalize in place; last block re-zeros g_stats for next replay
// ---------------------------------------------------------------------------
__global__ void k3(float* __restrict__ out,
                   const float* __restrict__ gamma,
                   const float* __restrict__ beta) {
    int e4 = blockIdx.x * blockDim.x + threadIdx.x;
    double n = (double)NPOS;
    if (e4 < NPOS * COUT / 4) {
        int o0 = (e4 * 4) & (COUT - 1);
        float4 v = ((const float4*)out)[e4];
        float r[4] = {v.x, v.y, v.z, v.w};
#pragma unroll
        for (int q = 0; q < 4; q++) {
            int o = o0 + q;
            double mean = g_stats[o] / n;
            double var  = g_stats[COUT + o] / n - mean * mean;
            float rstd = rsqrtf((float)var + EPSV);
            r[q] = gamma[o] * (r[q] - (float)mean) * rstd + beta[o];
        }
        ((float4*)out)[e4] = make_float4(r[0], r[1], r[2], r[3]);
    }
    __syncthreads();
    if (threadIdx.x == 0) {
        __threadfence();
        int old = atomicAdd(&g_sync, 1);
        if (old == (int)gridDim.x - 1) {
            for (int i = 0; i < 2 * COUT; i++) g_stats[i] = 0.0;
            __threadfence();
            g_sync = 0;
        }
    }
}

// ---------------------------------------------------------------------------
extern "C" void kernel_launch(void* const* d_in, const int* in_sizes, int n_in,
                              void* d_out, int out_size) {
    const float* times    = (const float*)d_in[0];
    const float* features = (const float*)d_in[1];
    const void*  mask     = d_in[2];
    const float* W1    = (const float*)d_in[3];
    const float* b1    = (const float*)d_in[4];
    const float* W2    = (const float*)d_in[5];
    const float* b2    = (const float*)d_in[6];
    const float* Wskip = (const float*)d_in[7];
    const float* bskip = (const float*)d_in[8];
    const float* gamma = (const float*)d_in[9];
    const float* beta  = (const float*)d_in[10];
    float* out = (float*)d_out;

    cudaFuncSetAttribute(kfused, cudaFuncAttributeMaxDynamicSharedMemorySize,
                         (int)sizeof(SmemT));

    kfused<<<NBLK, THREADS, sizeof(SmemT)>>>(times, features, mask, W1, b1,
                                             W2, b2, Wskip, bskip, out);
    k3<<<(NPOS * COUT / 4 + 255) / 256, 256>>>(out, gamma, beta);
}

// round 5
// speedup vs baseline: 5.0493x; 1.1475x over previous
#include <cuda_runtime.h>
#include <math.h>

#define BS 4
#define LEN 2048
#define CIN 32
#define COUT 32
#define HIDDIM 64
#define KTAP 8
#define PADL 7
#define NPOS (BS * LEN)
#define RDIM (CIN * HIDDIM)      // 2048
#define EPSV 1e-5f
#define NWB 16                    // positions / warps per block
#define THREADS 512
#define NBLK (NPOS / NWB)         // 512
#define MSPITCH 34                // u64 pitch per channel

typedef unsigned long long u64;

__device__ double g_stats[2 * COUT];
__device__ int    g_sync;

// ---- register-pure packed helpers ----
#define FMA2(d, a, b, c) \
    asm("fma.rn.f32x2 %0, %1, %2, %3;" : "=l"(d) : "l"(a), "l"(b), "l"(c))

__device__ __forceinline__ u64 pack2(float x, float y) {
    u64 d; asm("mov.b64 %0, {%1, %2};" : "=l"(d) : "f"(x), "f"(y)); return d;
}
__device__ __forceinline__ u64 packdup(float x) {
    u64 d; asm("mov.b64 %0, {%1, %1};" : "=l"(d) : "f"(x)); return d;
}
__device__ __forceinline__ void unpack2(u64 v, float& x, float& y) {
    asm("mov.b64 {%0, %1}, %2;" : "=f"(x), "=f"(y) : "l"(v));
}

// mask dtype hedge (byte 1 nonzero <=> 1-byte storage; else 4-byte words)
__device__ __forceinline__ bool mask_at(const void* m, int idx, bool byte_mode) {
    if (byte_mode) return ((const unsigned char*)m)[idx] != 0;
    return ((const unsigned int*)m)[idx] != 0u;
}

struct SmemT {
    float W1s[CIN * HIDDIM];      // row-major [i][j]                        8KB
    float b1s[HIDDIM];
    float b2s[CIN * COUT];        // 4KB
    float wsk[CIN * COUT];        // 4KB
    float bsk[COUT];
    float ff[NWB][CIN];           // 2KB
    float fs[NWB][CIN];           // 2KB
    float ssum[COUT], ssq[COUT];
    int   pflag[NWB];
    union alignas(16) {
        struct {
            float teu[NWB][CIN][KTAP];    // [i][k], tap pairs adjacent  16KB
            float hb[NWB][KTAP][HIDDIM];  // [k][j]                      32KB
        } a;
        float red[NWB][NWB][COUT];        // phase-B cross-warp partials 32KB
    } u;
    u64 Msu[NWB][CIN * MSPITCH];  // [c*34+q] = (M[c][2q], M[c][2q+1])  136KB
};

__global__ __launch_bounds__(THREADS, 1)
void kfused(const float* __restrict__ times,
            const float* __restrict__ features,
            const void*  __restrict__ mask,
            const float* __restrict__ W1,
            const float* __restrict__ b1,
            const float* __restrict__ W2,
            const float* __restrict__ b2,
            const float* __restrict__ Wskip,
            const float* __restrict__ bskip,
            float* __restrict__ out) {
    extern __shared__ char smem_raw[];
    SmemT* s = (SmemT*)smem_raw;

    int tid  = threadIdx.x;
    int wid  = tid >> 5;
    int lane = tid & 31;

    // ---- stage constants ----
    for (int i = tid; i < CIN * HIDDIM; i += THREADS) s->W1s[i] = W1[i];
    for (int i = tid; i < CIN * COUT; i += THREADS) {
        s->b2s[i] = b2[i];
        s->wsk[i] = Wskip[i];
    }
    if (tid < HIDDIM) s->b1s[tid] = b1[tid];
    if (tid < COUT) {
        s->bsk[tid]  = bskip[tid];
        s->ssum[tid] = 0.0f;
        s->ssq[tid]  = 0.0f;
    }
    __syncthreads();

    // ================= phase A: build M row (warp per position) ============
    int p = blockIdx.x * NWB + wid;
    int b = p >> 11;
    int t = p & (LEN - 1);

    bool byte_mode = ((const unsigned char*)mask)[1] != 0;
    bool mask_t = mask_at(mask, p, byte_mode);
    float t_here = times[p];

    s->ff[wid][lane] = features[(size_t)p * CIN + lane];

    // warp-uniform tap validity
    unsigned vmask = 0;
#pragma unroll
    for (int k = 0; k < KTAP; k++) {
        int idx = t - PADL + k;
        bool dm = mask_t && (idx >= 0);
        if (dm) dm = mask_at(mask, b * LEN + idx, byte_mode);
        if (dm) vmask |= (1u << k);
    }
    bool any = (vmask != 0);
    float fsum = 0.0f;

    if (any) {
        // --- te for all taps (lane = channel i) ---
        float inv_pos = __expf(-(float)(lane >> 1) * (9.210340371976184f / 16.0f));
        float phase   = (lane & 1) ? 1.5707963267948966f : 0.0f;
        float fk[KTAP];
#pragma unroll
        for (int k = 0; k < KTAP; k++) {
            int idx = t - PADL + k;
            float te = 0.0f;
            fk[k] = 0.0f;
            if ((vmask >> k) & 1) {
                float dt = t_here - times[b * LEN + idx];
                te = __sinf(dt * inv_pos + phase);
                fk[k] = features[(size_t)(b * LEN + idx) * CIN + lane];
            }
            s->u.a.teu[wid][lane][k] = te;
            fsum += fk[k];
        }
        __syncwarp();

        // --- h for all taps, i-outer (lane = j; also j+32) ---
        u64 hh[4][2];
#pragma unroll
        for (int k2 = 0; k2 < 4; k2++) {
            hh[k2][0] = packdup(s->b1s[lane]);
            hh[k2][1] = packdup(s->b1s[lane + 32]);
        }
#pragma unroll
        for (int i = 0; i < CIN; i++) {
            u64 w0 = packdup(s->W1s[i * HIDDIM + lane]);
            u64 w1 = packdup(s->W1s[i * HIDDIM + lane + 32]);
#pragma unroll
            for (int k2 = 0; k2 < 4; k2++) {
                u64 tp = *(const u64*)&s->u.a.teu[wid][i][2 * k2];  // bcast
                FMA2(hh[k2][0], tp, w0, hh[k2][0]);
                FMA2(hh[k2][1], tp, w1, hh[k2][1]);
            }
        }
        // relu + park [k][j]
#pragma unroll
        for (int k2 = 0; k2 < 4; k2++) {
            float a0, c0, a1, c1;
            unpack2(hh[k2][0], a0, c0);   // (h_{2k2}[lane], h_{2k2+1}[lane])
            unpack2(hh[k2][1], a1, c1);   // j = lane+32
            s->u.a.hb[wid][2 * k2][lane]          = fmaxf(a0, 0.0f);
            s->u.a.hb[wid][2 * k2 + 1][lane]      = fmaxf(c0, 0.0f);
            s->u.a.hb[wid][2 * k2][lane + 32]     = fmaxf(a1, 0.0f);
            s->u.a.hb[wid][2 * k2 + 1][lane + 32] = fmaxf(c1, 0.0f);
        }
        __syncwarp();

        // --- M update (lane = channel) ---
        u64 Macc[32];
#pragma unroll
        for (int q = 0; q < 32; q++) Macc[q] = 0ull;
#pragma unroll
        for (int k = 0; k < KTAP; k++) {
            if (!((vmask >> k) & 1)) continue;     // warp-uniform
            u64 f2 = packdup(fk[k]);
            const ulonglong2* hp2 = (const ulonglong2*)&s->u.a.hb[wid][k][0];
#pragma unroll
            for (int q2 = 0; q2 < 16; q2++) {
                ulonglong2 hp = hp2[q2];           // broadcast LDS.128
                FMA2(Macc[2 * q2],     f2, hp.x, Macc[2 * q2]);
                FMA2(Macc[2 * q2 + 1], f2, hp.y, Macc[2 * q2 + 1]);
            }
        }
#pragma unroll
        for (int q = 0; q < 32; q++) s->Msu[wid][lane * MSPITCH + q] = Macc[q];
    }
    s->fs[wid][lane] = fsum;
    if (lane == 0) s->pflag[wid] = any ? 1 : 0;
    __syncthreads();

    // ================= phase B: [16 x 2048] @ [2048 x 32] ==================
    u64 acc2[NWB];
#pragma unroll
    for (int q = 0; q < NWB; q++) acc2[q] = 0ull;

    for (int cc = 0; cc < 4; cc++) {
        int c   = 2 * wid + (cc >> 1);
        int j0  = (cc & 1) * 32;
        int jb2 = (cc & 1) * 16;
        u64 wq[16];
        const float* w2base = W2 + (size_t)j0 * (CIN * COUT) + c * COUT + lane;
#pragma unroll
        for (int q = 0; q < 16; q++) {
            float w0 = w2base[(2 * q) * (CIN * COUT)];
            float w1 = w2base[(2 * q + 1) * (CIN * COUT)];
            wq[q] = pack2(w0, w1);
        }
#pragma unroll
        for (int pp = 0; pp < NWB; pp++) {
            if (!s->pflag[pp]) continue;           // warp-uniform skip
            const ulonglong2* mp = (const ulonglong2*)&s->Msu[pp][c * MSPITCH + jb2];
#pragma unroll
            for (int q2 = 0; q2 < 8; q2++) {
                ulonglong2 m = mp[q2];             // broadcast LDS.128
                FMA2(acc2[pp], m.x, wq[2 * q2],     acc2[pp]);
                FMA2(acc2[pp], m.y, wq[2 * q2 + 1], acc2[pp]);
            }
        }
    }
#pragma unroll
    for (int pp = 0; pp < NWB; pp++) {
        float lo, hi;
        unpack2(acc2[pp], lo, hi);
        s->u.red[wid][pp][lane] = lo + hi;
    }
    __syncthreads();

    // ================= epilogue: warp wid finalizes its position ===========
    float o = 0.0f;
#pragma unroll
    for (int w = 0; w < NWB; w++) o += s->u.red[w][wid][lane];

    const float4* fs4 = (const float4*)&s->fs[wid][0];
    const float4* ff4 = (const float4*)&s->ff[wid][0];
#pragma unroll
    for (int q = 0; q < CIN / 4; q++) {
        float4 a  = fs4[q];
        float4 cf = ff4[q];
        o += a.x  * s->b2s[(q * 4 + 0) * 32 + lane];
        o += a.y  * s->b2s[(q * 4 + 1) * 32 + lane];
        o += a.z  * s->b2s[(q * 4 + 2) * 32 + lane];
        o += a.w  * s->b2s[(q * 4 + 3) * 32 + lane];
        o += cf.x * s->wsk[(q * 4 + 0) * 32 + lane];
        o += cf.y * s->wsk[(q * 4 + 1) * 32 + lane];
        o += cf.z * s->wsk[(q * 4 + 2) * 32 + lane];
        o += cf.w * s->wsk[(q * 4 + 3) * 32 + lane];
    }
    o += s->bsk[lane];

    out[(size_t)p * COUT + lane] = o;

    atomicAdd(&s->ssum[lane], o);
    atomicAdd(&s->ssq[lane], o * o);
    __syncthreads();
    if (tid < COUT) {
        atomicAdd(&g_stats[tid],        (double)s->ssum[tid]);
        atomicAdd(&g_stats[COUT + tid], (double)s->ssq[tid]);
    }
}

// ---------------------------------------------------------------------------
// K3: LayerNorm finalize; per-channel scale/bias computed once per block.
// Last-arriving block re-zeros g_stats for the next graph replay.
// ---------------------------------------------------------------------------
__global__ void k3(float* __restrict__ out,
                   const float* __restrict__ gamma,
                   const float* __restrict__ beta) {
    __shared__ float sc[COUT], sb[COUT];
    int tid = threadIdx.x;
    if (tid < COUT) {
        double n = (double)NPOS;
        double mean = g_stats[tid] / n;
        double var  = g_stats[COUT + tid] / n - mean * mean;
        float rstd = rsqrtf((float)var + EPSV);
        float g = gamma[tid] * rstd;
        sc[tid] = g;
        sb[tid] = beta[tid] - g * (float)mean;
    }
    __syncthreads();

    int e4 = blockIdx.x * blockDim.x + tid;
    if (e4 < NPOS * COUT / 4) {
        int o0 = (e4 * 4) & (COUT - 1);
        float4 v = ((const float4*)out)[e4];
        v.x = v.x * sc[o0]     + sb[o0];
        v.y = v.y * sc[o0 + 1] + sb[o0 + 1];
        v.z = v.z * sc[o0 + 2] + sb[o0 + 2];
        v.w = v.w * sc[o0 + 3] + sb[o0 + 3];
        ((float4*)out)[e4] = v;
    }
    __syncthreads();
    if (tid == 0) {
        __threadfence();
        int old = atomicAdd(&g_sync, 1);
        if (old == (int)gridDim.x - 1) {
            for (int i = 0; i < 2 * COUT; i++) g_stats[i] = 0.0;
            __threadfence();
            g_sync = 0;
        }
    }
}

// ---------------------------------------------------------------------------
extern "C" void kernel_launch(void* const* d_in, const int* in_sizes, int n_in,
                              void* d_out, int out_size) {
    const float* times    = (const float*)d_in[0];
    const float* features = (const float*)d_in[1];
    const void*  mask     = d_in[2];
    const float* W1    = (const float*)d_in[3];
    const float* b1    = (const float*)d_in[4];
    const float* W2    = (const float*)d_in[5];
    const float* b2    = (const float*)d_in[6];
    const float* Wskip = (const float*)d_in[7];
    const float* bskip = (const float*)d_in[8];
    const float* gamma = (const float*)d_in[9];
    const float* beta  = (const float*)d_in[10];
    float* out = (float*)d_out;

    cudaFuncSetAttribute(kfused, cudaFuncAttributeMaxDynamicSharedMemorySize,
                         (int)sizeof(SmemT));

    kfused<<<NBLK, THREADS, sizeof(SmemT)>>>(times, features, mask, W1, b1,
                                             W2, b2, Wskip, bskip, out);
    k3<<<(NPOS * COUT / 4 + 255) / 256, 256>>>(out, gamma, beta);
}